// round 7
// baseline (speedup 1.0000x reference)
#include <cuda_runtime.h>
#include <cstdint>

#define NN 20000
#define EE 320000
#define FF 8
#define TT 12
#define UU 256
#define FT 96   // FF*TT
#define FT4 24  // FT/4
#define EQ (EE / 4)   // edges per thread-quarter

// ---------------- device scratch ----------------
// g_dc: [0,NN) = deg-minus-selfloop (float bits), [NN,2NN) = cnt (int). Zero-init by memset.
__device__ unsigned g_dc[2 * NN];
__device__ int   g_off[NN + 1];
__device__ int   g_cur[NN];
__device__ uint2 g_edge[EE];        // (src, norm-bits) per dst-sorted slot
__device__ float g_Mz[FF * UU];     // prescaled by 0.5
__device__ float g_Mh[FF * UU];
__device__ float g_cz[UU];          // prescaled by 0.5
__device__ float g_ch[UU];
__device__ float g_p[TT];           // 0.5 * softmax(attention)

// ---------------- fast math ----------------
__device__ __forceinline__ float tanh_a(float x) {
    float y; asm("tanh.approx.f32 %0, %1;" : "=f"(y) : "f"(x)); return y;
}
__device__ __forceinline__ unsigned long long fma2(unsigned long long a,
                                                   unsigned long long b,
                                                   unsigned long long c) {
    unsigned long long d;
    asm("fma.rn.f32x2 %0, %1, %2, %3;" : "=l"(d) : "l"(a), "l"(b), "l"(c));
    return d;
}
__device__ __forceinline__ unsigned long long pack2(float lo, float hi) {
    unsigned long long r;
    asm("mov.b64 %0, {%1,%2};" : "=l"(r) : "f"(lo), "f"(hi));
    return r;
}
__device__ __forceinline__ void unpack2(unsigned long long v, float& lo, float& hi) {
    asm("mov.b64 {%0,%1}, %2;" : "=f"(lo), "=f"(hi) : "l"(v));
}
__device__ __forceinline__ float4 fma4s(float s, float4 v, float4 a) {
    a.x = fmaf(s, v.x, a.x); a.y = fmaf(s, v.y, a.y);
    a.z = fmaf(s, v.z, a.z); a.w = fmaf(s, v.w, a.w);
    return a;
}

// ---------------- phase 1: per-dst degree + edge counts (4 edges/thread) ----------------
__global__ void k_edges(const int* __restrict__ ei, const float* __restrict__ w) {
    int t = blockIdx.x * blockDim.x + threadIdx.x;
    if (t >= EQ) return;
    int   dst[4];
    float wv[4];
#pragma unroll
    for (int j = 0; j < 4; j++) {
        int e = t + j * EQ;
        dst[j] = __ldg(ei + EE + e);
        wv[j]  = __ldg(w + e);
    }
#pragma unroll
    for (int j = 0; j < 4; j++) {
        atomicAdd(reinterpret_cast<float*>(&g_dc[dst[j]]), wv[j]);
        atomicAdd(reinterpret_cast<int*>(&g_dc[NN + dst[j]]), 1);
    }
}

// ---------------- phase 2: scan (blk 0) + weight-fold (1..18) + softmax (19) ----------------
#define CHUNKS ((NN + 1023) / 1024)
__global__ void __launch_bounds__(1024) k_scanprep(
        const float* __restrict__ Wz, const float* __restrict__ Lzw,
        const float* __restrict__ bz, const float* __restrict__ Lzb,
        const float* __restrict__ Wh, const float* __restrict__ Lhw,
        const float* __restrict__ bh, const float* __restrict__ Lhb,
        const float* __restrict__ att) {
    int blk = blockIdx.x;
    int tid = threadIdx.x;

    if (blk == 0) {
        __shared__ int wsum[32];
        __shared__ int carry_s;
        int lane = tid & 31, wid = tid >> 5;
        int vv[CHUNKS];
#pragma unroll
        for (int c = 0; c < CHUNKS; c++) {           // front-batch all loads (MLP=20)
            int i = c * 1024 + tid;
            vv[c] = (i < NN) ? (int)g_dc[NN + i] : 0;
        }
        if (tid == 0) carry_s = 0;
        __syncthreads();
#pragma unroll
        for (int c = 0; c < CHUNKS; c++) {
            int i = c * 1024 + tid;
            int v = vv[c];
            int s = v;
#pragma unroll
            for (int d = 1; d < 32; d <<= 1) {
                int t2 = __shfl_up_sync(0xffffffffu, s, d);
                if (lane >= d) s += t2;
            }
            if (lane == 31) wsum[wid] = s;
            __syncthreads();
            if (wid == 0) {
                int ws = wsum[lane];
#pragma unroll
                for (int d = 1; d < 32; d <<= 1) {
                    int t2 = __shfl_up_sync(0xffffffffu, ws, d);
                    if (lane >= d) ws += t2;
                }
                wsum[lane] = ws;
            }
            __syncthreads();
            int warp_excl = (wid == 0) ? 0 : wsum[wid - 1];
            int excl = s - v + warp_excl + carry_s;
            if (i < NN) { g_off[i] = excl; g_cur[i] = excl; }
            int total = wsum[31];
            __syncthreads();
            if (tid == 0) carry_s += total;
            __syncthreads();
        }
        if (tid == 0) g_off[NN] = carry_s;
        return;
    }

    if (blk == 19) {
        if (tid == 0) {
            float m = -1e30f;
            for (int t = 0; t < TT; t++) m = fmaxf(m, att[t]);
            float e[TT], s = 0.0f;
            for (int t = 0; t < TT; t++) { e[t] = __expf(att[t] - m); s += e[t]; }
            float inv = 0.5f / s;                      // fold the 1/2 here
            for (int t = 0; t < TT; t++) g_p[t] = e[t] * inv;
        }
        return;
    }

    if (tid >= UU) return;
    int u = tid;
    bool isz = blk <= 9;
    int f = isz ? blk - 1 : blk - 10;
    const float* W  = isz ? Wz : Wh;
    const float* L  = isz ? Lzw : Lhw;
    const float* b  = isz ? bz : bh;
    const float* Lb = isz ? Lzb : Lhb;
    float* M = isz ? g_Mz : g_Mh;
    float* c = isz ? g_cz : g_ch;
    float scale = isz ? 0.5f : 1.0f;                   // tanh(az/2) prescale

    __shared__ float srow[UU];
    if (f < FF) {
        srow[u] = W[f * UU + u];
        __syncthreads();
        float s = 0.0f;
        for (int k = 0; k < UU; k++) s = fmaf(srow[k], L[k * UU + u], s);
        M[f * UU + u] = scale * s;
    } else {
        srow[u] = b[u];
        __syncthreads();
        float s = Lb[u];
        for (int k = 0; k < UU; k++) s = fmaf(srow[k], L[k * UU + u], s);
        c[u] = scale * s;
    }
}

// ---------------- phase 3: fill per-dst edge slots (4 edges/thread) ----------------
__global__ void k_fill(const int* __restrict__ ei, const float* __restrict__ w) {
    int t = blockIdx.x * blockDim.x + threadIdx.x;
    if (t >= EQ) return;
    int   src[4], dst[4];
    float wv[4];
#pragma unroll
    for (int j = 0; j < 4; j++) {
        int e = t + j * EQ;
        src[j] = __ldg(ei + e);
        dst[j] = __ldg(ei + EE + e);
        wv[j]  = __ldg(w + e);
    }
    float ds[4], dd[4];
#pragma unroll
    for (int j = 0; j < 4; j++) {
        ds[j] = __uint_as_float(g_dc[src[j]]) + 1.0f;
        dd[j] = __uint_as_float(g_dc[dst[j]]) + 1.0f;
    }
#pragma unroll
    for (int j = 0; j < 4; j++) {
        float nrm = rsqrtf(ds[j]) * wv[j] * rsqrtf(dd[j]);
        int p = atomicAdd(&g_cur[dst[j]], 1);
        g_edge[p] = make_uint2((unsigned)src[j], __float_as_uint(nrm));
    }
}

// ---------------- phase 4: fused gather + gates + epilogue ----------------
#define NPB 8
__global__ void __launch_bounds__(UU, 4) k_dense(const float4* __restrict__ x4,
                                                 const float* __restrict__ lin_w,
                                                 const float* __restrict__ lin_b,
                                                 float* __restrict__ out) {
    __shared__ __align__(16) float sY[NPB][FT];
    __shared__ float sH[NPB][UU];
    __shared__ __align__(16) float sp[TT];

    int u = threadIdx.x;
    int lane = u & 31;
    int wid = u >> 5;
    int n0 = blockIdx.x * NPB;

    // ---- gather: warp w aggregates node n0+w into sY[w] ----
    {
        int node = n0 + wid;
        int beg = g_off[node], end = g_off[node + 1];
        int ln = (lane < FT4) ? lane : 0;             // clamp: lanes 24-31 duplicate lane0
        float s = 1.0f / (__uint_as_float(g_dc[node]) + 1.0f);   // dinv^2 (self-loop)
        float4 a0 = __ldg(x4 + (size_t)node * FT4 + ln);
        a0.x *= s; a0.y *= s; a0.z *= s; a0.w *= s;
        float4 a1 = make_float4(0.f, 0.f, 0.f, 0.f);

        int i = beg;
        for (; i + 2 <= end; i += 2) {
            uint2 e0 = __ldg(&g_edge[i + 0]);
            uint2 e1 = __ldg(&g_edge[i + 1]);
            float4 v0 = __ldg(x4 + (size_t)e0.x * FT4 + ln);
            float4 v1 = __ldg(x4 + (size_t)e1.x * FT4 + ln);
            a0 = fma4s(__uint_as_float(e0.y), v0, a0);
            a1 = fma4s(__uint_as_float(e1.y), v1, a1);
        }
        if (i < end) {
            uint2 e = __ldg(&g_edge[i]);
            float4 v = __ldg(x4 + (size_t)e.x * FT4 + ln);
            a0 = fma4s(__uint_as_float(e.y), v, a0);
        }
        a0.x += a1.x; a0.y += a1.y; a0.z += a1.z; a0.w += a1.w;
        if (lane < FT4)
            reinterpret_cast<float4*>(sY[wid])[lane] = a0;
    }
    if (u < TT) sp[u] = g_p[u];                    // already 0.5*p
    __syncthreads();

    // ---- gates: thread u, loop nodes; LDS.128 (4 time-steps / iter) ----
    unsigned long long mz2[FF], mh2[FF];
#pragma unroll
    for (int f = 0; f < FF; f++) {
        float mz = g_Mz[f * UU + u];
        float mh = g_Mh[f * UU + u];
        mz2[f] = pack2(mz, mz);
        mh2[f] = pack2(mh, mh);
    }
    unsigned long long cz2, ch2;
    { float cz = g_cz[u], ch = g_ch[u]; cz2 = pack2(cz, cz); ch2 = pack2(ch, ch); }
    const float4* sp4 = reinterpret_cast<const float4*>(sp);

#pragma unroll
    for (int nn = 0; nn < NPB; nn++) {
        // ulonglong2 view: element g = f*3+tp2 holds t = {4tp2..4tp2+3} for feature f
        const ulonglong2* yrow = reinterpret_cast<const ulonglong2*>(sY[nn]);
        float acc = 0.0f;
#pragma unroll
        for (int tp2 = 0; tp2 < 3; tp2++) {
            unsigned long long az01 = cz2, az23 = cz2, ah01 = ch2, ah23 = ch2;
#pragma unroll
            for (int f = 0; f < FF; f++) {
                ulonglong2 y = yrow[f * 3 + tp2];     // one LDS.128 broadcast
                az01 = fma2(y.x, mz2[f], az01);
                az23 = fma2(y.y, mz2[f], az23);
                ah01 = fma2(y.x, mh2[f], ah01);
                ah23 = fma2(y.y, mh2[f], ah23);
            }
            float a0, a1, a2, a3, h0, h1, h2, h3;
            unpack2(az01, a0, a1); unpack2(az23, a2, a3);
            unpack2(ah01, h0, h1); unpack2(ah23, h2, h3);
            float4 q = sp4[tp2];                      // one LDS.128 broadcast
            float r0 = fmaf(-tanh_a(a0), q.x, q.x);   // q*(1-tanh(a/2)) = p*(1-sigmoid)
            float r1 = fmaf(-tanh_a(a1), q.y, q.y);
            float r2 = fmaf(-tanh_a(a2), q.z, q.z);
            float r3 = fmaf(-tanh_a(a3), q.w, q.w);
            acc = fmaf(r0, tanh_a(h0), acc);
            acc = fmaf(r1, tanh_a(h1), acc);
            acc = fmaf(r2, tanh_a(h2), acc);
            acc = fmaf(r3, tanh_a(h3), acc);
        }
        sH[nn][u] = fmaxf(acc, 0.0f);
    }
    __syncthreads();

    // ---- epilogue: warp w -> node n0+w ----
    {
        float part[TT];
#pragma unroll
        for (int t = 0; t < TT; t++) part[t] = 0.0f;
#pragma unroll
        for (int q = 0; q < 8; q++) {
            int k = lane + 32 * q;                  // conflict-free (lane-major)
            float h = sH[wid][k];
            const float4* wr = reinterpret_cast<const float4*>(lin_w + k * TT);
            float4 w0 = __ldg(wr + 0);
            float4 w1 = __ldg(wr + 1);
            float4 w2 = __ldg(wr + 2);
            part[0] = fmaf(h, w0.x, part[0]);  part[1]  = fmaf(h, w0.y, part[1]);
            part[2] = fmaf(h, w0.z, part[2]);  part[3]  = fmaf(h, w0.w, part[3]);
            part[4] = fmaf(h, w1.x, part[4]);  part[5]  = fmaf(h, w1.y, part[5]);
            part[6] = fmaf(h, w1.z, part[6]);  part[7]  = fmaf(h, w1.w, part[7]);
            part[8] = fmaf(h, w2.x, part[8]);  part[9]  = fmaf(h, w2.y, part[9]);
            part[10] = fmaf(h, w2.z, part[10]); part[11] = fmaf(h, w2.w, part[11]);
        }
#pragma unroll
        for (int d = 16; d > 0; d >>= 1)
#pragma unroll
            for (int t = 0; t < TT; t++)
                part[t] += __shfl_xor_sync(0xffffffffu, part[t], d);
        if (lane < TT)
            out[(size_t)(n0 + wid) * TT + lane] = part[lane] + __ldg(lin_b + lane);
    }
}

// ---------------- launcher ----------------
extern "C" void kernel_launch(void* const* d_in, const int* in_sizes, int n_in,
                              void* d_out, int out_size) {
    const float* x      = (const float*)d_in[0];
    const int*   ei     = (const int*)d_in[1];
    const float* ew     = (const float*)d_in[2];
    const float* att    = (const float*)d_in[3];
    const float* Wz     = (const float*)d_in[4];
    const float* bz     = (const float*)d_in[5];
    // d_in[6..7] (Wr, br) dead: r-gate multiplies H0 == 0
    const float* Wh     = (const float*)d_in[8];
    const float* bh     = (const float*)d_in[9];
    const float* Lzw    = (const float*)d_in[10];
    const float* Lzb    = (const float*)d_in[11];
    // d_in[12..13] (Lrw, Lrb) dead
    const float* Lhw    = (const float*)d_in[14];
    const float* Lhb    = (const float*)d_in[15];
    const float* lin_w  = (const float*)d_in[16];
    const float* lin_b  = (const float*)d_in[17];
    float* out = (float*)d_out;

    void* dc_ptr = nullptr;
    cudaGetSymbolAddress(&dc_ptr, g_dc);

    cudaMemsetAsync(dc_ptr, 0, 2 * NN * sizeof(unsigned));
    k_edges<<<(EQ + 255) / 256, 256>>>(ei, ew);
    k_scanprep<<<20, 1024>>>(Wz, Lzw, bz, Lzb, Wh, Lhw, bh, Lhb, att);
    k_fill<<<(EQ + 255) / 256, 256>>>(ei, ew);
    k_dense<<<NN / NPB, UU>>>((const float4*)x, lin_w, lin_b, out);
}